// round 15
// baseline (speedup 1.0000x reference)
#include <cuda_runtime.h>

#define EPS 1e-6f
#define Q 128
#define HW 65536            // 256*256
#define NCOLS 16            // columns per block (2 per warp)
#define THREADS 256
#define ASTRIDE 132         // words per column in staging arrays

__device__ float g_wt[Q];   // softmax(weights) * 128, precomputed once

__global__ void softmax_wt_kernel(const float* __restrict__ w) {
    int l = threadIdx.x;
    float v0 = w[l * 4 + 0], v1 = w[l * 4 + 1];
    float v2 = w[l * 4 + 2], v3 = w[l * 4 + 3];
    float m = fmaxf(fmaxf(v0, v1), fmaxf(v2, v3));
    #pragma unroll
    for (int o = 16; o; o >>= 1) m = fmaxf(m, __shfl_xor_sync(0xffffffffu, m, o));
    float e0 = expf(v0 - m), e1 = expf(v1 - m);
    float e2 = expf(v2 - m), e3 = expf(v3 - m);
    float s = e0 + e1 + e2 + e3;
    #pragma unroll
    for (int o = 16; o; o >>= 1) s += __shfl_xor_sync(0xffffffffu, s, o);
    float scale = 128.0f / s;
    g_wt[l * 4 + 0] = e0 * scale;
    g_wt[l * 4 + 1] = e1 * scale;
    g_wt[l * 4 + 2] = e2 * scale;
    g_wt[l * 4 + 3] = e3 * scale;
}

// orderable-uint transform: monotonic with float order (no NaN in inputs)
__device__ __forceinline__ unsigned ford(unsigned b) {
    return b ^ ((unsigned)(((int)b) >> 31) | 0x80000000u);
}

// unsigned compare-exchange helpers (predicated IMNMX form)
#define UCE_D(i,jj) { unsigned _a=v[i], _b=v[jj]; v[i]=max(_a,_b); v[jj]=min(_a,_b); }
#define UCE_A(i,jj) { unsigned _a=v[i], _b=v[jj]; v[i]=min(_a,_b); v[jj]=max(_a,_b); }
#define UCE_P(i,jj,p) { unsigned _a=v[i], _b=v[jj]; unsigned _mx=max(_a,_b), _mn=min(_a,_b); \
                        v[i]=(p)?_mx:_mn; v[jj]=(p)?_mn:_mx; }
#define UINREG_P(p) \
    UCE_P(0,4,p) UCE_P(1,5,p) UCE_P(2,6,p) UCE_P(3,7,p) \
    UCE_P(0,2,p) UCE_P(1,3,p) UCE_P(4,6,p) UCE_P(5,7,p) \
    UCE_P(0,1,p) UCE_P(2,3,p) UCE_P(4,5,p) UCE_P(6,7,p)
#define UXSTAGE(jm, km) { \
    _Pragma("unroll") \
    for (int _r = 0; _r < 8; _r++) { \
        unsigned _o = __shfl_xor_sync(0xffffffffu, v[_r], (jm)); \
        v[_r] = (km) ? max(v[_r], _o) : min(v[_r], _o); \
    } }

// ---------------------------------------------------------------------------
// 256 threads = 8 warps; each warp ranks TWO columns of 128 (lanes 0-15 ->
// col 2w, lanes 16-31 -> col 2w+1), 8 elements per lane (q = 8m+r).
// Keys = ford(x) with low 7 bits = 127-idx  ->  sort IS the rank+provenance.
// A holds originals (never modified); W receives scattered weights; the
// rsqrt multiply happens in the conflict-free output transpose.
// ---------------------------------------------------------------------------
__global__ void __launch_bounds__(THREADS, 7) rank_weight_kernel(
        const float* __restrict__ x, float* __restrict__ out) {
    __shared__ __align__(16) float A[NCOLS * ASTRIDE];  // originals (read-only after ph1)
    __shared__ __align__(16) float W[NCOLS * ASTRIDE];  // scattered weights

    int t    = threadIdx.x;
    int lane = t & 31;
    int w    = t >> 5;
    int h    = (lane >> 4) & 1;   // column half within warp
    int m    = lane & 15;         // lane index within column

    long long c0  = (long long)blockIdx.x * NCOLS;
    int       b   = (int)(c0 >> 16);
    int       rem = (int)(c0 & (HW - 1));
    const float* xb = x   + (long long)b * (Q * (long long)HW) + rem;
    float*       ob = out + (long long)b * (Q * (long long)HW) + rem;

    // ---- Phase 1: coalesced load, transpose into unswizzled SMEM ----
    // A[col][q] at word col*132 + q  (conflict-free for these access patterns)
    {
        int q = t >> 1, g = t & 1;
        float4 f0 = *reinterpret_cast<const float4*>(xb + (long long)q * HW + 4 * g);
        float4 f1 = *reinterpret_cast<const float4*>(xb + (long long)q * HW + 8 + 4 * g);
        float vv0[4] = {f0.x, f0.y, f0.z, f0.w};
        float vv1[4] = {f1.x, f1.y, f1.z, f1.w};
        #pragma unroll
        for (int j = 0; j < 4; j++) A[(4 * g + j) * ASTRIDE + q] = vv0[j];
        #pragma unroll
        for (int j = 0; j < 4; j++) A[(8 + 4 * g + j) * ASTRIDE + q] = vv1[j];
    }
    __syncthreads();

    // ---- Phase 2: read own column slice (q = 8m..8m+7), build keys ----
    int colw = (2 * w + h) * ASTRIDE;
    float4 ca = *reinterpret_cast<const float4*>(&A[colw + 8 * m]);
    float4 cb = *reinterpret_cast<const float4*>(&A[colw + 8 * m + 4]);
    unsigned v[8];
    {
        int base = 127 - 8 * m;
        float xs[8] = {ca.x, ca.y, ca.z, ca.w, cb.x, cb.y, cb.z, cb.w};
        #pragma unroll
        for (int r = 0; r < 8; r++)
            v[r] = (ford(__float_as_uint(xs[r])) & 0xFFFFFF80u) + (unsigned)(base - r);
    }

    // ---- bitonic sort over i = 8m + r, descending on keys ----
    UCE_D(0,1) UCE_A(2,3) UCE_D(4,5) UCE_A(6,7)                 // k=2
    UCE_D(0,2) UCE_D(1,3) UCE_A(4,6) UCE_A(5,7)                 // k=4
    UCE_D(0,1) UCE_D(2,3) UCE_A(4,5) UCE_A(6,7)
    {   bool d8 = (m & 1) == 0;                                  // k=8
        UINREG_P(d8)
    }
    {   bool k16 = (m & 2) == 0;                                 // k=16
        UXSTAGE(1, k16 == ((m & 1) == 0))
        UINREG_P(k16)
    }
    {   bool k32 = (m & 4) == 0;                                 // k=32
        UXSTAGE(2, k32 == ((m & 2) == 0))
        UXSTAGE(1, k32 == ((m & 1) == 0))
        UINREG_P(k32)
    }
    {   bool k64 = (m & 8) == 0;                                 // k=64
        UXSTAGE(4, k64 == ((m & 4) == 0))
        UXSTAGE(2, k64 == ((m & 2) == 0))
        UXSTAGE(1, k64 == ((m & 1) == 0))
        UINREG_P(k64)
    }
    UXSTAGE(8, (m & 8) == 0)                                     // k=128
    UXSTAGE(4, (m & 4) == 0)
    UXSTAGE(2, (m & 2) == 0)
    UXSTAGE(1, (m & 1) == 0)
    UCE_D(0,4) UCE_D(1,5) UCE_D(2,6) UCE_D(3,7)
    UCE_D(0,2) UCE_D(1,3) UCE_D(4,6) UCE_D(5,7)
    UCE_D(0,1) UCE_D(2,3) UCE_D(4,5) UCE_D(6,7)

    // ---- weights for ranks 8m..8m+7 (loaded AFTER sort to cut live regs) ----
    float wv[8];
    #pragma unroll
    for (int r = 0; r < 8; r++) wv[r] = __ldg(&g_wt[8 * m + r]);

    // ---- clobber detection: adjacent sorted keys with equal high-25 bits ----
    unsigned knext = __shfl_down_sync(0xffffffffu, v[0], 1);   // next lane's first
    unsigned kprev = __shfl_up_sync(0xffffffffu, v[7], 1);     // prev lane's last
    bool fl0 = (v[0] ^ v[1]) < 128u;
    bool fl1 = (v[1] ^ v[2]) < 128u;
    bool fl2 = (v[2] ^ v[3]) < 128u;
    bool fl3 = (v[3] ^ v[4]) < 128u;
    bool fl4 = (v[4] ^ v[5]) < 128u;
    bool fl5 = (v[5] ^ v[6]) < 128u;
    bool fl6 = (v[6] ^ v[7]) < 128u;
    bool flagB = (m < 15) && ((v[7] ^ knext) < 128u);
    unsigned fpv = __shfl_up_sync(0xffffffffu, (unsigned)flagB, 1);
    bool fprev = (m > 0) && (fpv != 0u);

    bool fwp[8] = {fprev, fl0, fl1, fl2, fl3, fl4, fl5, fl6};
    bool fwn[8] = {fl0, fl1, fl2, fl3, fl4, fl5, fl6, flagB};
    bool anyf = false, badf = false;
    #pragma unroll
    for (int r = 0; r < 8; r++) { anyf |= (fwp[r] | fwn[r]); badf |= (fwp[r] & fwn[r]); }

    unsigned fb = __ballot_sync(0xffffffffu, anyf);
    if (fb) {
        unsigned bb = __ballot_sync(0xffffffffu, badf);
        if (bb) {
            // run >= 3 somewhere (ultra rare): exact recompute of all ranks
            #pragma unroll 1
            for (int r = 0; r < 8; r++) {
                int idx = (int)((~v[r]) & 127u);
                unsigned us = ford(__float_as_uint(A[colw + idx]));
                int gt = 0, eq = 0;
                for (int jj = 0; jj < Q; jj++) {
                    unsigned ua = ford(__float_as_uint(A[colw + jj]));
                    gt += (ua > us) ? 1 : 0;
                    eq += ((ua == us) && (jj < idx)) ? 1 : 0;
                }
                wv[r] = g_wt[gt + eq];
            }
        } else {
            // pair runs only: exact 2-element fix (rare, predicated)
            #pragma unroll
            for (int r = 0; r < 8; r++) {
                if (fwp[r] | fwn[r]) {
                    bool lo = fwp[r];
                    unsigned pk = lo ? (r > 0 ? v[r - 1] : kprev)
                                     : (r < 7 ? v[r + 1] : knext);
                    int idx  = (int)((~v[r]) & 127u);
                    int pidx = (int)((~pk)   & 127u);
                    unsigned us = ford(__float_as_uint(A[colw + idx]));
                    unsigned up = ford(__float_as_uint(A[colw + pidx]));
                    bool mefirst = (us > up) || ((us == up) && (idx < pidx));
                    int p    = 8 * m + r;
                    int pmin = lo ? p - 1 : p;
                    wv[r] = g_wt[mefirst ? pmin : pmin + 1];
                }
            }
        }
    }

    // ---- scatter weights only: W[idx] = wt[rank]; A stays untouched ----
    #pragma unroll
    for (int r = 0; r < 8; r++)
        W[colw + (int)((~v[r]) & 127u)] = wv[r];
    __syncthreads();

    // ---- Phase 4: fused rsqrt + transpose back, coalesced store ----
    {
        int q = t >> 1, g = t & 1;
        float o[8];
        #pragma unroll
        for (int j = 0; j < 4; j++) {
            int aw = (4 * g + j) * ASTRIDE + q;
            float xv = A[aw];
            float rs;
            asm("rsqrt.approx.f32 %0, %1;" : "=f"(rs) : "f"(__fmaf_rn(xv, xv, EPS)));
            o[j] = W[aw] * rs;
        }
        #pragma unroll
        for (int j = 0; j < 4; j++) {
            int aw = (8 + 4 * g + j) * ASTRIDE + q;
            float xv = A[aw];
            float rs;
            asm("rsqrt.approx.f32 %0, %1;" : "=f"(rs) : "f"(__fmaf_rn(xv, xv, EPS)));
            o[4 + j] = W[aw] * rs;
        }
        *reinterpret_cast<float4*>(ob + (long long)q * HW + 4 * g) =
            make_float4(o[0], o[1], o[2], o[3]);
        *reinterpret_cast<float4*>(ob + (long long)q * HW + 8 + 4 * g) =
            make_float4(o[4], o[5], o[6], o[7]);
    }
}

// ---------------------------------------------------------------------------
extern "C" void kernel_launch(void* const* d_in, const int* in_sizes, int n_in,
                              void* d_out, int out_size) {
    const float* x  = (const float*)d_in[0];
    const float* wt = (const float*)d_in[1];
    if (n_in >= 2 && in_sizes[0] == Q) {  // defensive: metadata order swap
        const float* tmp = x; x = wt; wt = tmp;
    }
    float* out = (float*)d_out;

    softmax_wt_kernel<<<1, 32>>>(wt);

    int total_cols = 8 * HW;               // 524288
    int blocks = total_cols / NCOLS;       // 32768
    rank_weight_kernel<<<blocks, THREADS>>>(x, out);
}

// round 16
// speedup vs baseline: 1.0420x; 1.0420x over previous
#include <cuda_runtime.h>

#define EPS 1e-6f
#define Q 128
#define HW 65536            // 256*256
#define NCOLS 16            // columns per block (2 per warp)
#define THREADS 256
#define ASTRIDE 132         // words per column in staging arrays

__device__ float g_wt[Q];   // softmax(weights) * 128, precomputed once

__global__ void softmax_wt_kernel(const float* __restrict__ w) {
    int l = threadIdx.x;
    float v0 = w[l * 4 + 0], v1 = w[l * 4 + 1];
    float v2 = w[l * 4 + 2], v3 = w[l * 4 + 3];
    float m = fmaxf(fmaxf(v0, v1), fmaxf(v2, v3));
    #pragma unroll
    for (int o = 16; o; o >>= 1) m = fmaxf(m, __shfl_xor_sync(0xffffffffu, m, o));
    float e0 = expf(v0 - m), e1 = expf(v1 - m);
    float e2 = expf(v2 - m), e3 = expf(v3 - m);
    float s = e0 + e1 + e2 + e3;
    #pragma unroll
    for (int o = 16; o; o >>= 1) s += __shfl_xor_sync(0xffffffffu, s, o);
    float scale = 128.0f / s;
    g_wt[l * 4 + 0] = e0 * scale;
    g_wt[l * 4 + 1] = e1 * scale;
    g_wt[l * 4 + 2] = e2 * scale;
    g_wt[l * 4 + 3] = e3 * scale;
}

// orderable-uint transform: monotonic with float order (no NaN in inputs)
__device__ __forceinline__ unsigned ford(unsigned b) {
    return b ^ ((unsigned)(((int)b) >> 31) | 0x80000000u);
}

// unsigned compare-exchange helpers (predicated IMNMX form)
#define UCE_D(i,jj) { unsigned _a=v[i], _b=v[jj]; v[i]=max(_a,_b); v[jj]=min(_a,_b); }
#define UCE_A(i,jj) { unsigned _a=v[i], _b=v[jj]; v[i]=min(_a,_b); v[jj]=max(_a,_b); }
#define UCE_P(i,jj,p) { unsigned _a=v[i], _b=v[jj]; unsigned _mx=max(_a,_b), _mn=min(_a,_b); \
                        v[i]=(p)?_mx:_mn; v[jj]=(p)?_mn:_mx; }
#define UINREG_P(p) \
    UCE_P(0,4,p) UCE_P(1,5,p) UCE_P(2,6,p) UCE_P(3,7,p) \
    UCE_P(0,2,p) UCE_P(1,3,p) UCE_P(4,6,p) UCE_P(5,7,p) \
    UCE_P(0,1,p) UCE_P(2,3,p) UCE_P(4,5,p) UCE_P(6,7,p)
#define UXSTAGE(jm, km) { \
    _Pragma("unroll") \
    for (int _r = 0; _r < 8; _r++) { \
        unsigned _o = __shfl_xor_sync(0xffffffffu, v[_r], (jm)); \
        v[_r] = (km) ? max(v[_r], _o) : min(v[_r], _o); \
    } }

// ---------------------------------------------------------------------------
// 256 threads = 8 warps; each warp ranks TWO columns of 128 (lanes 0-15 ->
// col 2w, lanes 16-31 -> col 2w+1), 8 elements per lane (q = 8m+r).
// Keys = ford(x) with low 7 bits = 127-idx  ->  sort IS the rank+provenance.
// A holds originals (read-only after phase 1); W receives scattered weights;
// the rsqrt multiply is fused into the conflict-free output transpose.
// ---------------------------------------------------------------------------
__global__ void __launch_bounds__(THREADS, 6) rank_weight_kernel(
        const float* __restrict__ x, float* __restrict__ out) {
    __shared__ __align__(16) float A[NCOLS * ASTRIDE];  // originals
    __shared__ __align__(16) float W[NCOLS * ASTRIDE];  // scattered weights

    int t    = threadIdx.x;
    int lane = t & 31;
    int w    = t >> 5;
    int h    = (lane >> 4) & 1;   // column half within warp
    int m    = lane & 15;         // lane index within column

    long long c0  = (long long)blockIdx.x * NCOLS;
    int       b   = (int)(c0 >> 16);
    int       rem = (int)(c0 & (HW - 1));
    const float* xb = x   + (long long)b * (Q * (long long)HW) + rem;
    float*       ob = out + (long long)b * (Q * (long long)HW) + rem;

    // ---- Phase 1: coalesced load, transpose into unswizzled SMEM ----
    // A[col][q] at word col*132 + q  (conflict-free for these access patterns)
    {
        int q = t >> 1, g = t & 1;
        float4 f0 = *reinterpret_cast<const float4*>(xb + (long long)q * HW + 4 * g);
        float4 f1 = *reinterpret_cast<const float4*>(xb + (long long)q * HW + 8 + 4 * g);
        float vv0[4] = {f0.x, f0.y, f0.z, f0.w};
        float vv1[4] = {f1.x, f1.y, f1.z, f1.w};
        #pragma unroll
        for (int j = 0; j < 4; j++) A[(4 * g + j) * ASTRIDE + q] = vv0[j];
        #pragma unroll
        for (int j = 0; j < 4; j++) A[(8 + 4 * g + j) * ASTRIDE + q] = vv1[j];
    }
    __syncthreads();

    // ---- Phase 2: read own column slice (q = 8m..8m+7), build keys ----
    int colw = (2 * w + h) * ASTRIDE;
    float4 ca = *reinterpret_cast<const float4*>(&A[colw + 8 * m]);
    float4 cb = *reinterpret_cast<const float4*>(&A[colw + 8 * m + 4]);
    unsigned v[8];
    {
        int base = 127 - 8 * m;
        float xs[8] = {ca.x, ca.y, ca.z, ca.w, cb.x, cb.y, cb.z, cb.w};
        #pragma unroll
        for (int r = 0; r < 8; r++)
            v[r] = (ford(__float_as_uint(xs[r])) & 0xFFFFFF80u) + (unsigned)(base - r);
    }

    // ---- bitonic sort over i = 8m + r, descending on keys ----
    UCE_D(0,1) UCE_A(2,3) UCE_D(4,5) UCE_A(6,7)                 // k=2
    UCE_D(0,2) UCE_D(1,3) UCE_A(4,6) UCE_A(5,7)                 // k=4
    UCE_D(0,1) UCE_D(2,3) UCE_A(4,5) UCE_A(6,7)
    {   bool d8 = (m & 1) == 0;                                  // k=8
        UINREG_P(d8)
    }
    {   bool k16 = (m & 2) == 0;                                 // k=16
        UXSTAGE(1, k16 == ((m & 1) == 0))
        UINREG_P(k16)
    }
    {   bool k32 = (m & 4) == 0;                                 // k=32
        UXSTAGE(2, k32 == ((m & 2) == 0))
        UXSTAGE(1, k32 == ((m & 1) == 0))
        UINREG_P(k32)
    }
    {   bool k64 = (m & 8) == 0;                                 // k=64
        UXSTAGE(4, k64 == ((m & 4) == 0))
        UXSTAGE(2, k64 == ((m & 2) == 0))
        UXSTAGE(1, k64 == ((m & 1) == 0))
        UINREG_P(k64)
    }
    UXSTAGE(8, (m & 8) == 0)                                     // k=128
    UXSTAGE(4, (m & 4) == 0)
    UXSTAGE(2, (m & 2) == 0)
    UXSTAGE(1, (m & 1) == 0)
    UCE_D(0,4) UCE_D(1,5) UCE_D(2,6) UCE_D(3,7)
    UCE_D(0,2) UCE_D(1,3) UCE_D(4,6) UCE_D(5,7)
    UCE_D(0,1) UCE_D(2,3) UCE_D(4,5) UCE_D(6,7)

    // ---- weights for ranks 8m..8m+7: two vector loads (8 wf, short-lived) ----
    float wv[8];
    {
        float4 wta = *reinterpret_cast<const float4*>(&g_wt[8 * m]);
        float4 wtb = *reinterpret_cast<const float4*>(&g_wt[8 * m + 4]);
        wv[0] = wta.x; wv[1] = wta.y; wv[2] = wta.z; wv[3] = wta.w;
        wv[4] = wtb.x; wv[5] = wtb.y; wv[6] = wtb.z; wv[7] = wtb.w;
    }

    // ---- clobber detection: adjacent sorted keys with equal high-25 bits ----
    unsigned knext = __shfl_down_sync(0xffffffffu, v[0], 1);   // next lane's first
    unsigned kprev = __shfl_up_sync(0xffffffffu, v[7], 1);     // prev lane's last
    bool fl0 = (v[0] ^ v[1]) < 128u;
    bool fl1 = (v[1] ^ v[2]) < 128u;
    bool fl2 = (v[2] ^ v[3]) < 128u;
    bool fl3 = (v[3] ^ v[4]) < 128u;
    bool fl4 = (v[4] ^ v[5]) < 128u;
    bool fl5 = (v[5] ^ v[6]) < 128u;
    bool fl6 = (v[6] ^ v[7]) < 128u;
    bool flagB = (m < 15) && ((v[7] ^ knext) < 128u);
    unsigned fpv = __shfl_up_sync(0xffffffffu, (unsigned)flagB, 1);
    bool fprev = (m > 0) && (fpv != 0u);

    bool fwp[8] = {fprev, fl0, fl1, fl2, fl3, fl4, fl5, fl6};
    bool fwn[8] = {fl0, fl1, fl2, fl3, fl4, fl5, fl6, flagB};
    bool anyf = false, badf = false;
    #pragma unroll
    for (int r = 0; r < 8; r++) { anyf |= (fwp[r] | fwn[r]); badf |= (fwp[r] & fwn[r]); }

    unsigned fb = __ballot_sync(0xffffffffu, anyf);
    if (fb) {
        unsigned bb = __ballot_sync(0xffffffffu, badf);
        if (bb) {
            // run >= 3 somewhere (ultra rare): exact recompute of all ranks
            #pragma unroll 1
            for (int r = 0; r < 8; r++) {
                int idx = (int)((~v[r]) & 127u);
                unsigned us = ford(__float_as_uint(A[colw + idx]));
                int gt = 0, eq = 0;
                for (int jj = 0; jj < Q; jj++) {
                    unsigned ua = ford(__float_as_uint(A[colw + jj]));
                    gt += (ua > us) ? 1 : 0;
                    eq += ((ua == us) && (jj < idx)) ? 1 : 0;
                }
                wv[r] = g_wt[gt + eq];
            }
        } else {
            // pair runs only: exact 2-element fix (rare, predicated)
            #pragma unroll
            for (int r = 0; r < 8; r++) {
                if (fwp[r] | fwn[r]) {
                    bool lo = fwp[r];
                    unsigned pk = lo ? (r > 0 ? v[r - 1] : kprev)
                                     : (r < 7 ? v[r + 1] : knext);
                    int idx  = (int)((~v[r]) & 127u);
                    int pidx = (int)((~pk)   & 127u);
                    unsigned us = ford(__float_as_uint(A[colw + idx]));
                    unsigned up = ford(__float_as_uint(A[colw + pidx]));
                    bool mefirst = (us > up) || ((us == up) && (idx < pidx));
                    int p    = 8 * m + r;
                    int pmin = lo ? p - 1 : p;
                    wv[r] = g_wt[mefirst ? pmin : pmin + 1];
                }
            }
        }
    }

    // ---- scatter weights only: W[idx] = wt[rank]; A stays untouched ----
    #pragma unroll
    for (int r = 0; r < 8; r++)
        W[colw + (int)((~v[r]) & 127u)] = wv[r];
    __syncthreads();

    // ---- Phase 4: fused rsqrt + transpose back, coalesced store ----
    {
        int q = t >> 1, g = t & 1;
        float o[8];
        #pragma unroll
        for (int j = 0; j < 4; j++) {
            int aw = (4 * g + j) * ASTRIDE + q;
            float xv = A[aw];
            float rs;
            asm("rsqrt.approx.f32 %0, %1;" : "=f"(rs) : "f"(__fmaf_rn(xv, xv, EPS)));
            o[j] = W[aw] * rs;
        }
        #pragma unroll
        for (int j = 0; j < 4; j++) {
            int aw = (8 + 4 * g + j) * ASTRIDE + q;
            float xv = A[aw];
            float rs;
            asm("rsqrt.approx.f32 %0, %1;" : "=f"(rs) : "f"(__fmaf_rn(xv, xv, EPS)));
            o[4 + j] = W[aw] * rs;
        }
        *reinterpret_cast<float4*>(ob + (long long)q * HW + 4 * g) =
            make_float4(o[0], o[1], o[2], o[3]);
        *reinterpret_cast<float4*>(ob + (long long)q * HW + 8 + 4 * g) =
            make_float4(o[4], o[5], o[6], o[7]);
    }
}

// ---------------------------------------------------------------------------
extern "C" void kernel_launch(void* const* d_in, const int* in_sizes, int n_in,
                              void* d_out, int out_size) {
    const float* x  = (const float*)d_in[0];
    const float* wt = (const float*)d_in[1];
    if (n_in >= 2 && in_sizes[0] == Q) {  // defensive: metadata order swap
        const float* tmp = x; x = wt; wt = tmp;
    }
    float* out = (float*)d_out;

    softmax_wt_kernel<<<1, 32>>>(wt);

    int total_cols = 8 * HW;               // 524288
    int blocks = total_cols / NCOLS;       // 32768
    rank_weight_kernel<<<blocks, THREADS>>>(x, out);
}